// round 1
// baseline (speedup 1.0000x reference)
#include <cuda_runtime.h>
#include <cstdint>

#define S   512
#define BB  64
#define TT  512
#define VV  2048
#define CL  8      // CTAs per cluster
#define JC  64     // columns (next-states) per CTA
#define NB  4      // batches per cluster
#define NTHREADS 256

// Scratch (no runtime allocation allowed)
__device__ float g_T[S * S];        // row-softmax of trans_logits, row-major [i][j]
__device__ float g_logEt[VV * S];   // log_softmax(emit) transposed: [v][s]

// ---------------- cluster helpers ----------------
__device__ __forceinline__ unsigned cluster_rank() {
    unsigned r; asm("mov.u32 %0, %%cluster_ctarank;" : "=r"(r)); return r;
}
__device__ __forceinline__ void cluster_sync_all() {
    asm volatile("barrier.cluster.arrive.aligned;" ::: "memory");
    asm volatile("barrier.cluster.wait.aligned;" ::: "memory");
}
__device__ __forceinline__ float dsmem_ld(const float* p, unsigned rank) {
    unsigned a = (unsigned)__cvta_generic_to_shared((void*)p);
    unsigned ra;
    asm("mapa.shared::cluster.u32 %0, %1, %2;" : "=r"(ra) : "r"(a), "r"(rank));
    float v;
    asm volatile("ld.shared::cluster.f32 %0, [%1];" : "=f"(v) : "r"(ra) : "memory");
    return v;
}

// ---------------- block reduce (256 threads / 8 warps) ----------------
template <bool IS_MAX>
__device__ __forceinline__ float blk_reduce(float v, float* scratch) {
    #pragma unroll
    for (int o = 16; o; o >>= 1) {
        float w = __shfl_xor_sync(~0u, v, o);
        v = IS_MAX ? fmaxf(v, w) : v + w;
    }
    int warp = threadIdx.x >> 5, lane = threadIdx.x & 31;
    if (lane == 0) scratch[warp] = v;
    __syncthreads();
    if (threadIdx.x < 8) {
        v = scratch[threadIdx.x];
        #pragma unroll
        for (int o = 4; o; o >>= 1) {
            float w = __shfl_xor_sync(0xffu, v, o);
            v = IS_MAX ? fmaxf(v, w) : v + w;
        }
        if (threadIdx.x == 0) scratch[0] = v;
    }
    __syncthreads();
    v = scratch[0];
    __syncthreads();
    return v;
}

// ---------------- prep: T = softmax(trans_logits, axis=-1) ----------------
__global__ void prep_trans(const float* __restrict__ trans) {
    __shared__ float scratch[8];
    const int row = blockIdx.x;
    const float* x = trans + row * S;
    const int tid = threadIdx.x;

    float m = -1e30f;
    for (int i = tid; i < S; i += NTHREADS) m = fmaxf(m, x[i]);
    m = blk_reduce<true>(m, scratch);

    float s = 0.f;
    for (int i = tid; i < S; i += NTHREADS) s += __expf(x[i] - m);
    s = blk_reduce<false>(s, scratch);

    const float inv = 1.0f / s;
    for (int i = tid; i < S; i += NTHREADS)
        g_T[row * S + i] = __expf(x[i] - m) * inv;
}

// ---------------- prep: logEt[v][s] = log_softmax(emit[s,:])[v] ----------------
__global__ void prep_emit(const float* __restrict__ emit) {
    __shared__ float scratch[8];
    const int row = blockIdx.x;          // state s
    const float* x = emit + row * VV;
    const int tid = threadIdx.x;

    float m = -1e30f;
    for (int i = tid; i < VV; i += NTHREADS) m = fmaxf(m, x[i]);
    m = blk_reduce<true>(m, scratch);

    float s = 0.f;
    for (int i = tid; i < VV; i += NTHREADS) s += __expf(x[i] - m);
    s = blk_reduce<false>(s, scratch);

    const float lse = m + __logf(s);
    for (int i = tid; i < VV; i += NTHREADS)
        g_logEt[i * S + row] = x[i] - lse;
}

// ---------------- main: persistent clustered forward scan ----------------
// grid = 128 CTAs (16 clusters of 8). Cluster c owns batches [4c, 4c+4).
// CTA rank r owns columns [64r, 64r+64) and its 128KB T slice in smem.
__global__ void __cluster_dims__(CL, 1, 1) __launch_bounds__(NTHREADS, 1)
hmm_main(const int* __restrict__ value, const float* __restrict__ prior,
         float* __restrict__ out) {
    extern __shared__ float sm[];
    float* T_s   = sm;                    // S*JC       = 32768
    float* p_s   = T_s + S * JC;          // NB*S       = 2048
    float* vbuf  = p_s + NB * S;          // 2*NB*JC    = 512   (double-buffered)
    float* mbuf  = vbuf + 2 * NB * JC;    // 2*NB       = 8     (double-buffered)
    float* red   = mbuf + 2 * NB;         // 16*NB*JC   = 4096  (GEMV partials)
    float* wmaxb = red + 16 * NB * JC;    // 8
    float* m_s   = wmaxb + 8;             // NB
    float* c_s   = m_s + NB;              // NB
    float* lpl   = c_s + NB;              // 1

    const unsigned r = cluster_rank();
    const int clus  = blockIdx.x >> 3;
    const int b0    = clus * NB;
    const int jbase = (int)r * JC;
    const int tid   = threadIdx.x;
    const int b     = tid >> 6;           // batch slot 0..3
    const int j     = tid & 63;           // local column
    const int warp  = tid >> 5;
    const int lane  = tid & 31;
    const int jq    = tid & 15;           // column quad for GEMV
    const int ip    = tid >> 4;           // i-partition (16 x 32 rows)

    // Load this CTA's T column slice: T_s[i*64 + jj] = T[i][jbase+jj]
    for (int idx = tid; idx < S * JC; idx += NTHREADS) {
        int i  = idx >> 6;
        int jj = idx & 63;
        T_s[idx] = g_T[i * S + jbase + jj];
    }

    // prior logsumexp (redundant per CTA, trivial)
    {
        float m = -1e30f;
        for (int i = tid; i < S; i += NTHREADS) m = fmaxf(m, prior[i]);
        m = blk_reduce<true>(m, wmaxb);
        float s = 0.f;
        for (int i = tid; i < S; i += NTHREADS) s += __expf(prior[i] - m);
        s = blk_reduce<false>(s, wmaxb);
        if (tid == 0) lpl[0] = m + __logf(s);
        if (tid < NB) c_s[tid] = 0.f;
        __syncthreads();
    }
    const float lp_lse = lpl[0];

    int bufsel = 0;

    #pragma unroll 1
    for (int t = 0; t < TT; ++t) {
        // emission for this thread's (b, j) — issued early to hide latency
        const int obs = value[(b0 + b) * TT + t];
        const float em = g_logEt[obs * S + jbase + j];

        float vv;
        if (t == 0) {
            vv = em + prior[jbase + j] - lp_lse;
        } else {
            // GEMV slice: q[b][j] = sum_i p[b][i] * T_s[i][j]
            float4 a0 = {0,0,0,0}, a1 = {0,0,0,0}, a2 = {0,0,0,0}, a3 = {0,0,0,0};
            const float4* T4 = (const float4*)T_s;
            const int ibeg = ip * 32;
            #pragma unroll 8
            for (int i = ibeg; i < ibeg + 32; ++i) {
                float4 tv = T4[i * 16 + jq];
                float q0 = p_s[i];
                float q1 = p_s[S + i];
                float q2 = p_s[2 * S + i];
                float q3 = p_s[3 * S + i];
                a0.x += q0 * tv.x; a0.y += q0 * tv.y; a0.z += q0 * tv.z; a0.w += q0 * tv.w;
                a1.x += q1 * tv.x; a1.y += q1 * tv.y; a1.z += q1 * tv.z; a1.w += q1 * tv.w;
                a2.x += q2 * tv.x; a2.y += q2 * tv.y; a2.z += q2 * tv.z; a2.w += q2 * tv.w;
                a3.x += q3 * tv.x; a3.y += q3 * tv.y; a3.z += q3 * tv.z; a3.w += q3 * tv.w;
            }
            float4* R4 = (float4*)red;
            R4[(ip * NB + 0) * 16 + jq] = a0;
            R4[(ip * NB + 1) * 16 + jq] = a1;
            R4[(ip * NB + 2) * 16 + jq] = a2;
            R4[(ip * NB + 3) * 16 + jq] = a3;
            __syncthreads();
            float q = 0.f;
            #pragma unroll
            for (int k = 0; k < 16; ++k) q += red[(k * NB + b) * JC + j];
            vv = em + __logf(q);
        }

        // publish v slice + local max for the cluster exchange
        vbuf[bufsel * NB * JC + tid] = vv;
        float wm = vv;
        #pragma unroll
        for (int o = 16; o; o >>= 1) wm = fmaxf(wm, __shfl_xor_sync(~0u, wm, o));
        if (lane == 0) wmaxb[warp] = wm;
        __syncthreads();
        if (tid < NB) {
            float lm = fmaxf(wmaxb[2 * tid], wmaxb[2 * tid + 1]);
            mbuf[bufsel * NB + tid] = lm;
        }

        cluster_sync_all();

        // global max per batch (across 8 ranks), update running constant
        if (tid < NB) {
            float gm = -1e30f;
            #pragma unroll
            for (int rr = 0; rr < CL; ++rr)
                gm = fmaxf(gm, dsmem_ld(&mbuf[bufsel * NB + tid], rr));
            m_s[tid] = gm;
            c_s[tid] += gm;
        }
        __syncthreads();

        // rebuild full normalized p[b][0..511] locally from peer v slices
        for (int idx = tid; idx < NB * S; idx += NTHREADS) {
            int bb = idx >> 9;
            int i  = idx & 511;
            int rr = i >> 6;
            int jj = i & 63;
            float pv = dsmem_ld(&vbuf[bufsel * NB * JC + bb * JC + jj], (unsigned)rr);
            p_s[idx] = __expf(pv - m_s[bb]);
        }
        __syncthreads();
        bufsel ^= 1;
    }

    cluster_sync_all();   // keep peer smem alive until everyone is done reading

    // answer[b] = C[b] + log(sum_i p[b][i]); every CTA has identical p/C — rank 0 writes
    if (r == 0) {
        for (int bb = 0; bb < NB; ++bb) {
            float s = 0.f;
            for (int i = tid; i < S; i += NTHREADS) s += p_s[bb * S + i];
            s = blk_reduce<false>(s, wmaxb);
            if (tid == 0) out[b0 + bb] = c_s[bb] + __logf(s);
        }
    }
}

static const int SMEM_BYTES =
    (S * JC + NB * S + 2 * NB * JC + 2 * NB + 16 * NB * JC + 8 + NB + NB + 4) * 4;

extern "C" void kernel_launch(void* const* d_in, const int* in_sizes, int n_in,
                              void* d_out, int out_size) {
    (void)in_sizes; (void)n_in; (void)out_size;
    const int*   value = (const int*)d_in[0];
    const float* prior = (const float*)d_in[1];
    const float* trans = (const float*)d_in[2];
    const float* emit  = (const float*)d_in[3];
    float* out = (float*)d_out;

    prep_trans<<<S, NTHREADS>>>(trans);
    prep_emit<<<S, NTHREADS>>>(emit);

    cudaFuncSetAttribute(hmm_main, cudaFuncAttributeMaxDynamicSharedMemorySize, SMEM_BYTES);
    hmm_main<<<(BB / NB) * CL, NTHREADS, SMEM_BYTES>>>(value, prior, out);
}

// round 2
// speedup vs baseline: 1.0040x; 1.0040x over previous
#include <cuda_runtime.h>
#include <cstdint>

#define S   512
#define BB  64
#define TT  512
#define VV  2048
#define CL  8      // CTAs per cluster
#define JC  64     // columns (next-states) per CTA
#define NB  4      // batches per cluster
#define NTHREADS 256

// Scratch (no runtime allocation allowed)
__device__ float g_T[S * S];        // row-softmax of trans_logits, row-major [i][j]
__device__ float g_logEt[VV * S];   // log_softmax(emit) transposed: [v][s]

// ---------------- cluster helpers ----------------
__device__ __forceinline__ unsigned cluster_rank() {
    unsigned r; asm("mov.u32 %0, %%cluster_ctarank;" : "=r"(r)); return r;
}
__device__ __forceinline__ void cluster_sync_all() {
    asm volatile("barrier.cluster.arrive.aligned;" ::: "memory");
    asm volatile("barrier.cluster.wait.aligned;" ::: "memory");
}
__device__ __forceinline__ float dsmem_ld(const float* p, unsigned rank) {
    unsigned a = (unsigned)__cvta_generic_to_shared((void*)p);
    unsigned ra;
    asm("mapa.shared::cluster.u32 %0, %1, %2;" : "=r"(ra) : "r"(a), "r"(rank));
    float v;
    asm volatile("ld.shared::cluster.f32 %0, [%1];" : "=f"(v) : "r"(ra) : "memory");
    return v;
}

// ---------------- block reduce (256 threads / 8 warps) ----------------
template <bool IS_MAX>
__device__ __forceinline__ float blk_reduce(float v, float* scratch) {
    #pragma unroll
    for (int o = 16; o; o >>= 1) {
        float w = __shfl_xor_sync(~0u, v, o);
        v = IS_MAX ? fmaxf(v, w) : v + w;
    }
    int warp = threadIdx.x >> 5, lane = threadIdx.x & 31;
    if (lane == 0) scratch[warp] = v;
    __syncthreads();
    if (threadIdx.x < 8) {
        v = scratch[threadIdx.x];
        #pragma unroll
        for (int o = 4; o; o >>= 1) {
            float w = __shfl_xor_sync(0xffu, v, o);
            v = IS_MAX ? fmaxf(v, w) : v + w;
        }
        if (threadIdx.x == 0) scratch[0] = v;
    }
    __syncthreads();
    v = scratch[0];
    __syncthreads();
    return v;
}

// ---------------- prep: T = softmax(trans_logits, axis=-1) ----------------
__global__ void prep_trans(const float* __restrict__ trans) {
    __shared__ float scratch[8];
    const int row = blockIdx.x;
    const float* x = trans + row * S;
    const int tid = threadIdx.x;

    float m = -1e30f;
    for (int i = tid; i < S; i += NTHREADS) m = fmaxf(m, x[i]);
    m = blk_reduce<true>(m, scratch);

    float s = 0.f;
    for (int i = tid; i < S; i += NTHREADS) s += __expf(x[i] - m);
    s = blk_reduce<false>(s, scratch);

    const float inv = 1.0f / s;
    for (int i = tid; i < S; i += NTHREADS)
        g_T[row * S + i] = __expf(x[i] - m) * inv;
}

// ---------------- prep: logEt[v][s] = log_softmax(emit[s,:])[v] ----------------
__global__ void prep_emit(const float* __restrict__ emit) {
    __shared__ float scratch[8];
    const int row = blockIdx.x;          // state s
    const float* x = emit + row * VV;
    const int tid = threadIdx.x;

    float m = -1e30f;
    for (int i = tid; i < VV; i += NTHREADS) m = fmaxf(m, x[i]);
    m = blk_reduce<true>(m, scratch);

    float s = 0.f;
    for (int i = tid; i < VV; i += NTHREADS) s += __expf(x[i] - m);
    s = blk_reduce<false>(s, scratch);

    const float lse = m + __logf(s);
    for (int i = tid; i < VV; i += NTHREADS)
        g_logEt[i * S + row] = x[i] - lse;
}

// ---------------- main: persistent clustered forward scan ----------------
// grid = 128 CTAs (16 clusters of 8). Cluster c owns batches [4c, 4c+4).
// CTA rank r owns columns [64r, 64r+64) and its 128KB T slice in smem.
__global__ void __cluster_dims__(CL, 1, 1) __launch_bounds__(NTHREADS, 1)
hmm_main(const int* __restrict__ value, const float* __restrict__ prior,
         float* __restrict__ out) {
    extern __shared__ float sm[];
    float* T_s   = sm;                    // S*JC       = 32768
    float* p_s   = T_s + S * JC;          // NB*S       = 2048
    float* vbuf  = p_s + NB * S;          // 2*NB*JC    = 512   (double-buffered)
    float* mbuf  = vbuf + 2 * NB * JC;    // 2*NB       = 8     (double-buffered)
    float* red   = mbuf + 2 * NB;         // 16*NB*JC   = 4096  (GEMV partials)
    float* wmaxb = red + 16 * NB * JC;    // 8
    float* m_s   = wmaxb + 8;             // NB
    float* c_s   = m_s + NB;              // NB
    float* lpl   = c_s + NB;              // 1

    const unsigned r = cluster_rank();
    const int clus  = blockIdx.x >> 3;
    const int b0    = clus * NB;
    const int jbase = (int)r * JC;
    const int tid   = threadIdx.x;
    const int b     = tid >> 6;           // batch slot 0..3
    const int j     = tid & 63;           // local column
    const int warp  = tid >> 5;
    const int lane  = tid & 31;
    const int jq    = tid & 15;           // column quad for GEMV
    const int ip    = tid >> 4;           // i-partition (16 x 32 rows)

    // Load this CTA's T column slice: T_s[i*64 + jj] = T[i][jbase+jj]
    for (int idx = tid; idx < S * JC; idx += NTHREADS) {
        int i  = idx >> 6;
        int jj = idx & 63;
        T_s[idx] = g_T[i * S + jbase + jj];
    }

    // prior logsumexp (redundant per CTA, trivial)
    {
        float m = -1e30f;
        for (int i = tid; i < S; i += NTHREADS) m = fmaxf(m, prior[i]);
        m = blk_reduce<true>(m, wmaxb);
        float s = 0.f;
        for (int i = tid; i < S; i += NTHREADS) s += __expf(prior[i] - m);
        s = blk_reduce<false>(s, wmaxb);
        if (tid == 0) lpl[0] = m + __logf(s);
        if (tid < NB) c_s[tid] = 0.f;
        __syncthreads();
    }
    const float lp_lse = lpl[0];

    int bufsel = 0;

    #pragma unroll 1
    for (int t = 0; t < TT; ++t) {
        // emission for this thread's (b, j) — issued early to hide latency
        const int obs = value[(b0 + b) * TT + t];
        const float em = g_logEt[obs * S + jbase + j];

        float vv;
        if (t == 0) {
            vv = em + prior[jbase + j] - lp_lse;
        } else {
            // GEMV slice: q[b][j] = sum_i p[b][i] * T_s[i][j]
            float4 a0 = {0,0,0,0}, a1 = {0,0,0,0}, a2 = {0,0,0,0}, a3 = {0,0,0,0};
            const float4* T4 = (const float4*)T_s;
            const int ibeg = ip * 32;
            #pragma unroll 8
            for (int i = ibeg; i < ibeg + 32; ++i) {
                float4 tv = T4[i * 16 + jq];
                float q0 = p_s[i];
                float q1 = p_s[S + i];
                float q2 = p_s[2 * S + i];
                float q3 = p_s[3 * S + i];
                a0.x += q0 * tv.x; a0.y += q0 * tv.y; a0.z += q0 * tv.z; a0.w += q0 * tv.w;
                a1.x += q1 * tv.x; a1.y += q1 * tv.y; a1.z += q1 * tv.z; a1.w += q1 * tv.w;
                a2.x += q2 * tv.x; a2.y += q2 * tv.y; a2.z += q2 * tv.z; a2.w += q2 * tv.w;
                a3.x += q3 * tv.x; a3.y += q3 * tv.y; a3.z += q3 * tv.z; a3.w += q3 * tv.w;
            }
            float4* R4 = (float4*)red;
            R4[(ip * NB + 0) * 16 + jq] = a0;
            R4[(ip * NB + 1) * 16 + jq] = a1;
            R4[(ip * NB + 2) * 16 + jq] = a2;
            R4[(ip * NB + 3) * 16 + jq] = a3;
            __syncthreads();
            float q = 0.f;
            #pragma unroll
            for (int k = 0; k < 16; ++k) q += red[(k * NB + b) * JC + j];
            vv = em + __logf(q);
        }

        // publish v slice + local max for the cluster exchange
        vbuf[bufsel * NB * JC + tid] = vv;
        float wm = vv;
        #pragma unroll
        for (int o = 16; o; o >>= 1) wm = fmaxf(wm, __shfl_xor_sync(~0u, wm, o));
        if (lane == 0) wmaxb[warp] = wm;
        __syncthreads();
        if (tid < NB) {
            float lm = fmaxf(wmaxb[2 * tid], wmaxb[2 * tid + 1]);
            mbuf[bufsel * NB + tid] = lm;
        }

        cluster_sync_all();

        // global max per batch (across 8 ranks), update running constant
        if (tid < NB) {
            float gm = -1e30f;
            #pragma unroll
            for (int rr = 0; rr < CL; ++rr)
                gm = fmaxf(gm, dsmem_ld(&mbuf[bufsel * NB + tid], rr));
            m_s[tid] = gm;
            c_s[tid] += gm;
        }
        __syncthreads();

        // rebuild full normalized p[b][0..511] locally from peer v slices
        for (int idx = tid; idx < NB * S; idx += NTHREADS) {
            int bb = idx >> 9;
            int i  = idx & 511;
            int rr = i >> 6;
            int jj = i & 63;
            float pv = dsmem_ld(&vbuf[bufsel * NB * JC + bb * JC + jj], (unsigned)rr);
            p_s[idx] = __expf(pv - m_s[bb]);
        }
        __syncthreads();
        bufsel ^= 1;
    }

    cluster_sync_all();   // keep peer smem alive until everyone is done reading

    // answer[b] = C[b] + log(sum_i p[b][i]); every CTA has identical p/C — rank 0 writes
    if (r == 0) {
        for (int bb = 0; bb < NB; ++bb) {
            float s = 0.f;
            for (int i = tid; i < S; i += NTHREADS) s += p_s[bb * S + i];
            s = blk_reduce<false>(s, wmaxb);
            if (tid == 0) out[b0 + bb] = c_s[bb] + __logf(s);
        }
    }
}

static const int SMEM_BYTES =
    (S * JC + NB * S + 2 * NB * JC + 2 * NB + 16 * NB * JC + 8 + NB + NB + 4) * 4;

extern "C" void kernel_launch(void* const* d_in, const int* in_sizes, int n_in,
                              void* d_out, int out_size) {
    (void)in_sizes; (void)n_in; (void)out_size;
    const int*   value = (const int*)d_in[0];
    const float* prior = (const float*)d_in[1];
    const float* trans = (const float*)d_in[2];
    const float* emit  = (const float*)d_in[3];
    float* out = (float*)d_out;

    prep_trans<<<S, NTHREADS>>>(trans);
    prep_emit<<<S, NTHREADS>>>(emit);

    cudaFuncSetAttribute(hmm_main, cudaFuncAttributeMaxDynamicSharedMemorySize, SMEM_BYTES);
    hmm_main<<<(BB / NB) * CL, NTHREADS, SMEM_BYTES>>>(value, prior, out);
}